// round 9
// baseline (speedup 1.0000x reference)
#include <cuda_runtime.h>

// ---------------------------------------------------------------------------
// SynthMorphLoss fused single-kernel, spatially partitioned:
//   blocks [0,554):    26-bin histograms of both int32 label maps
//   blocks [554,1184): diffusion regularizer, z-marching columns
//   last block to finish: dice + means -> out[3], reset scratch.
// Inputs: d_in[0] int32[6881280], d_in[1] int32[6881280],
//         d_in[2] float32[20643840] = [1,3,160,192,224]
// Output: float32[3] = (total, similarity, smoothness)
// ---------------------------------------------------------------------------

#define T      256
#define GRID   1184         // 148 SMs x 8 blocks -> one wave
#define HBLK   554          // histogram blocks; diffusion gets 630
#define NBINS  26
#define NW     21           // 3 types * 7 packed words per thread
#define PL     10752        // z-plane stride in float4 (192*56)
#define CHUNK  32           // z-planes per diffusion unit (160 = 5*32)

__device__ unsigned g_hist[3 * NBINS];  // [fixed_vol | moving_vol | inter]
__device__ double   g_sums[3];          // [sum dz^2, sum dy^2, sum dx^2]
__device__ unsigned g_done;

__global__ __launch_bounds__(T) void fused_k(const int* __restrict__ f,
                                             const int* __restrict__ m,
                                             const float* __restrict__ vf,
                                             float* __restrict__ out,
                                             int n4lab) {
    __shared__ unsigned s[NW * T];      // 21.5 KB (hist blocks only use it)
    __shared__ float    r[3][T / 32];
    __shared__ int      slast;
    const int tid = threadIdx.x;
    const int bid = blockIdx.x;

    if (bid < HBLK) {
        // ================= histogram partition =================
        #pragma unroll
        for (int w = 0; w < NW; w++) s[w * T + tid] = 0u;
        __syncthreads();

        const int4* f4 = (const int4*)f;
        const int4* m4 = (const int4*)m;
        const int step = HBLK * T;

        auto proc = [&](int fa, int mb) {
            unsigned fu = min((unsigned)fa, 25u);
            unsigned mu = min((unsigned)mb, 25u);
            s[(fu >> 2) * T + tid]        += 1u << ((fu & 3u) * 8u);
            s[(7u + (mu >> 2)) * T + tid] += 1u << ((mu & 3u) * 8u);
            if (fu == mu)
                s[(14u + (fu >> 2)) * T + tid] += 1u << ((fu & 3u) * 8u);
        };

        int i = bid * T + tid;
        for (; i + step < n4lab; i += 2 * step) {   // 4 LDG.128 in flight
            int4 a0 = f4[i],        b0 = m4[i];
            int4 a1 = f4[i + step], b1 = m4[i + step];
            proc(a0.x, b0.x); proc(a0.y, b0.y); proc(a0.z, b0.z); proc(a0.w, b0.w);
            proc(a1.x, b1.x); proc(a1.y, b1.y); proc(a1.z, b1.z); proc(a1.w, b1.w);
        }
        if (i < n4lab) {
            int4 a = f4[i], b = m4[i];
            proc(a.x, b.x); proc(a.y, b.y); proc(a.z, b.z); proc(a.w, b.w);
        }
        __syncthreads();

        // block reduce: 21 threads, whole-word dual-lane accumulation.
        // 16-bit lanes hold <= 256*52 = 13312 < 65535: no overflow.
        if (tid < NW) {
            const unsigned* row = &s[tid * T];
            unsigned a02 = 0u, a13 = 0u;
            #pragma unroll 8
            for (int kk = 0; kk < T; kk++) {        // skew -> few bank conflicts
                unsigned wv = row[(kk + tid * 12) & (T - 1)];
                a02 += wv & 0x00FF00FFu;
                a13 += (wv >> 8) & 0x00FF00FFu;
            }
            int type = tid / 7, wi = tid - type * 7;
            int b0 = wi * 4;
            unsigned c0 = a02 & 0xFFFFu, c1 = a13 & 0xFFFFu;
            unsigned c2 = a02 >> 16,     c3 = a13 >> 16;
            if (b0 + 0 < NBINS && c0) atomicAdd(&g_hist[type * NBINS + b0 + 0], c0);
            if (b0 + 1 < NBINS && c1) atomicAdd(&g_hist[type * NBINS + b0 + 1], c1);
            if (b0 + 2 < NBINS && c2) atomicAdd(&g_hist[type * NBINS + b0 + 2], c2);
            if (b0 + 3 < NBINS && c3) atomicAdd(&g_hist[type * NBINS + b0 + 3], c3);
            __threadfence();
        }
    } else {
        // ================= diffusion partition: z-marching =================
        // unit u -> (c, zc, y, x4); exactly one unit per thread (630*256 units)
        const float4* v4 = (const float4*)vf;
        const int u = (bid - HBLK) * T + tid;
        float sx = 0.f, sy = 0.f, sz = 0.f;

        int x4 = u % 56;
        int t  = u / 56;
        int y  = t % 192;
        int cz = t / 192;              // 0..14 = c*5 + zc
        int zc = cz % 5;
        int c  = cz / 5;
        int z0 = zc * CHUNK;
        int idx = ((c * 160 + z0) * 192 + y) * 56 + x4;

        const bool do_y = (y < 191);
        const bool do_x = (x4 < 55);
        const int zmax = (zc < 4) ? CHUNK : (CHUNK - 1);   // # of z-pairs

        auto xyp = [&](const float4& v, int id) {
            float d0 = v.y - v.x, d1 = v.z - v.y, d2 = v.w - v.z;
            sx += d0 * d0 + d1 * d1 + d2 * d2;
            if (do_x) {
                float nx = __ldg(&vf[4 * id + 4]);
                float d = nx - v.w;
                sx += d * d;
            }
            if (do_y) {
                float4 uu = v4[id + 56];
                float a = uu.x - v.x, b = uu.y - v.y,
                      cc = uu.z - v.z, e = uu.w - v.w;
                sy += a * a + b * b + cc * cc + e * e;
            }
        };

        float4 p = v4[idx];
        xyp(p, idx);                    // plane z0
        #pragma unroll 4
        for (int k = 1; k <= zmax; k++) {
            idx += PL;
            float4 cu = v4[idx];
            float a = cu.x - p.x, b = cu.y - p.y,
                  cc = cu.z - p.z, e = cu.w - p.w;
            sz += a * a + b * b + cc * cc + e * e;
            if (k < CHUNK) xyp(cu, idx);    // plane z0+CHUNK belongs to next unit
            p = cu;
        }

        // block reduce -> 3 double atomics
        #pragma unroll
        for (int o = 16; o > 0; o >>= 1) {
            sz += __shfl_down_sync(0xffffffffu, sz, o);
            sy += __shfl_down_sync(0xffffffffu, sy, o);
            sx += __shfl_down_sync(0xffffffffu, sx, o);
        }
        int lane = tid & 31, w = tid >> 5;
        if (lane == 0) { r[0][w] = sz; r[1][w] = sy; r[2][w] = sx; }
        __syncthreads();
        if (tid == 0) {
            float tz = 0.f, ty = 0.f, tx = 0.f;
            #pragma unroll
            for (int k = 0; k < T / 32; k++) { tz += r[0][k]; ty += r[1][k]; tx += r[2][k]; }
            atomicAdd(&g_sums[0], (double)tz);
            atomicAdd(&g_sums[1], (double)ty);
            atomicAdd(&g_sums[2], (double)tx);
            __threadfence();
        }
    }

    // ================= completion + finalize in last block =================
    __syncthreads();
    if (tid == 0) {
        unsigned prev = atomicAdd(&g_done, 1u);
        slast = (prev == (unsigned)(GRID - 1));
    }
    __syncthreads();
    if (!slast) return;
    __threadfence();                    // acquire: all blocks' REDs visible

    if (tid < 32) {
        volatile unsigned* vh = g_hist;
        volatile double*   vs = g_sums;
        double term = 0.0;
        if (tid >= 1 && tid < 26) {     // class 0 ignored; 25 parallel fp64 divs
            double inter = (double)vh[2 * NBINS + tid];
            double fv    = (double)vh[tid];
            double mv    = (double)vh[NBINS + tid];
            term = (2.0 * inter + 1e-5) / (fv + mv + 1e-5);
        }
        #pragma unroll
        for (int o = 16; o > 0; o >>= 1)
            term += __shfl_down_sync(0xffffffffu, term, o);
        if (tid == 0) {
            double sim = 1.0 - term / 25.0;
            // denominators: 3*159*192*224, 3*160*191*224, 3*160*192*223
            double sm = (vs[0] / 20514816.0 +
                         vs[1] / 20536320.0 +
                         vs[2] / 20551680.0) / 3.0;
            out[0] = (float)(sim + sm);
            out[1] = (float)sim;
            out[2] = (float)sm;
        }
    }
    __syncthreads();                    // reads done before resets
    if (tid < 3 * NBINS) g_hist[tid] = 0u;      // self-clean for next replay
    if (tid >= 96 && tid < 99) g_sums[tid - 96] = 0.0;
    if (tid == 128) g_done = 0u;
}

// ---------------------------------------------------------------------------
extern "C" void kernel_launch(void* const* d_in, const int* in_sizes, int n_in,
                              void* d_out, int out_size) {
    const int*   fixedmap = (const int*)d_in[0];
    const int*   moving   = (const int*)d_in[1];
    const float* vf       = (const float*)d_in[2];
    float*       out      = (float*)d_out;

    int n4lab = in_sizes[0] / 4;   // 1,720,320 int4

    fused_k<<<GRID, T>>>(fixedmap, moving, vf, out, n4lab);
}